// round 1
// baseline (speedup 1.0000x reference)
#include <cuda_runtime.h>
#include <math.h>
#include <float.h>

#define XS 2048
#define NN 4096
#define ZS 64
#define DD 6208
#define NV4 1552          // DD/4
#define TK 16
#define ZTK 8
#define EPSF 1e-9f
#define RNDF 0.5f
#define NCHUNK 32

// ---------------- device scratch (no allocations allowed) ----------------
__device__ __align__(16) float g_inpt[DD];
__device__ float g_w[DD];                 // (ages-1)/ages
__device__ float g_resp[DD];
__device__ __align__(16) float g_mix_x[DD];
__device__ __align__(16) float g_mix_y[DD];
__device__ __align__(16) float g_mix_z[DD];
__device__ float g_mixx_part[NCHUNK][DD]; // deterministic partial sums
__device__ float g_yval[TK + 1];
__device__ int   g_yrow[TK + 1];
__device__ float g_zval[ZTK + 1];
__device__ int   g_zrow[ZTK + 1];
__device__ float g_inv_dx;

// ---------------- helpers ----------------
__device__ __forceinline__ float blockReduceSumB(float v) {
    __shared__ float red[8];
    __shared__ float bcast;
    int lane = threadIdx.x & 31;
    int wid  = threadIdx.x >> 5;
#pragma unroll
    for (int o = 16; o > 0; o >>= 1) v += __shfl_down_sync(0xffffffffu, v, o);
    if (lane == 0) red[wid] = v;
    __syncthreads();
    if (wid == 0) {
        float x = (lane < 8) ? red[lane] : 0.0f;
#pragma unroll
        for (int o = 4; o > 0; o >>= 1) x += __shfl_down_sync(0xffffffffu, x, o);
        if (lane == 0) bcast = x;
    }
    __syncthreads();
    return bcast;
}

// ---------------- K1: build inpt, weights, zero final, copy ages ----------------
__global__ void k_init(const float* __restrict__ x, const float* __restrict__ z,
                       const float* __restrict__ yresp, const float* __restrict__ ages,
                       float* __restrict__ out_z, float* __restrict__ out_final,
                       float* __restrict__ out_ages) {
    int i = blockIdx.x * 256 + threadIdx.x;
    if (i < DD) {
        float v;
        if (i < XS)           v = x[i];
        else if (i < XS + NN) v = yresp[i - XS];
        else                  v = z[i - XS - NN];
        g_inpt[i] = v;
        float a = ages[i];
        g_w[i] = (a - 1.0f) / a;
        out_final[i] = 0.0f;
        out_ages[i]  = a;
    }
    if (i < ZS) out_z[i] = 0.0f;
}

// ---------------- K2: matvec + fused copy (skip rows < XS-1, rewritten later) ----------------
__global__ void k_matvec(const float4* __restrict__ neu4, float* __restrict__ out_neu) {
    int row = blockIdx.x;
    const float4* src = neu4 + (size_t)row * NV4;
    float4* dst = reinterpret_cast<float4*>(out_neu) + (size_t)row * NV4;
    const float4* ip = reinterpret_cast<const float4*>(g_inpt);
    int t = threadIdx.x;
    float acc = 0.0f;
    bool docopy = (row >= XS - 1);
#pragma unroll
    for (int j = 0; j < 7; j++) {
        int c = t + j * 256;
        if (c < NV4) {
            float4 v = __ldg(src + c);
            float4 w = ip[c];
            acc = fmaf(v.x, w.x, acc);
            acc = fmaf(v.y, w.y, acc);
            acc = fmaf(v.z, w.z, acc);
            acc = fmaf(v.w, w.w, acc);
            if (docopy) __stcs(dst + c, v);
        }
    }
    float tot = blockReduceSumB(acc);
    if (t == 0) g_resp[row] = tot;
}

// ---------------- K3: mix_x column partial sums (deterministic chunks) ----------------
__global__ void k_mixx(const float* __restrict__ neurons) {
    int c = blockIdx.x * 256 + threadIdx.x;
    int chunk = blockIdx.y;
    if (c >= DD) return;
    int r0 = chunk * 64;
    int r1 = min(r0 + 64, XS - 1);
    float acc = 0.0f;
    for (int r = r0; r < r1; r++)
        acc = fmaf(g_w[r], __ldg(&neurons[(size_t)r * DD + c]), acc);
    g_mixx_part[chunk][c] = acc;
}

// ---------------- K4: top-k (y:17, z:9), x-max, scalar finals ----------------
__global__ void k_topk(const float* __restrict__ ages, float* __restrict__ out_z,
                       float* __restrict__ out_final, float* __restrict__ out_ages) {
    __shared__ float sv[NN];
    __shared__ float rv[256];
    __shared__ int   ri[256];
    int t = threadIdx.x;

    // ---- Y top-17 (descending, ties -> lowest index, matching lax.top_k) ----
    for (int i = t; i < NN; i += 256) sv[i] = g_resp[XS + i];
    __syncthreads();
    for (int k = 0; k < TK + 1; k++) {
        float bv = -FLT_MAX; int bi = 1 << 30;
        for (int i = t; i < NN; i += 256) {
            float v = sv[i];
            if (v > bv || (v == bv && i < bi)) { bv = v; bi = i; }
        }
        rv[t] = bv; ri[t] = bi;
        __syncthreads();
        for (int s = 128; s > 0; s >>= 1) {
            if (t < s) {
                float ov = rv[t + s]; int oi = ri[t + s];
                if (ov > rv[t] || (ov == rv[t] && oi < ri[t])) { rv[t] = ov; ri[t] = oi; }
            }
            __syncthreads();
        }
        if (t == 0) { g_yval[k] = rv[0]; g_yrow[k] = XS + ri[0]; sv[ri[0]] = -FLT_MAX; }
        __syncthreads();
    }

    // ---- Z top-9 ----
    if (t < ZS) sv[t] = g_resp[XS + NN + t];
    __syncthreads();
    for (int k = 0; k < ZTK + 1; k++) {
        float bv = -FLT_MAX; int bi = 1 << 30;
        if (t < ZS) { bv = sv[t]; bi = t; }
        rv[t] = bv; ri[t] = bi;
        __syncthreads();
        for (int s = 128; s > 0; s >>= 1) {
            if (t < s) {
                float ov = rv[t + s]; int oi = ri[t + s];
                if (ov > rv[t] || (ov == rv[t] && oi < ri[t])) { rv[t] = ov; ri[t] = oi; }
            }
            __syncthreads();
        }
        if (t == 0) { g_zval[k] = rv[0]; g_zrow[k] = XS + NN + ri[0]; sv[ri[0]] = -FLT_MAX; }
        __syncthreads();
    }

    // ---- X max + all-zero flag ----
    float m = -FLT_MAX; int nz = 0;
    for (int i = t; i < XS; i += 256) { float v = g_resp[i]; m = fmaxf(m, v); nz |= (v != 0.0f); }
    rv[t] = m; ri[t] = nz;
    __syncthreads();
    for (int s = 128; s > 0; s >>= 1) {
        if (t < s) { rv[t] = fmaxf(rv[t], rv[t + s]); ri[t] |= ri[t + s]; }
        __syncthreads();
    }

    if (t == 0) {
        float tx = ri[0] ? 0.0f : 1.0f;
        g_inv_dx = 1.0f / (rv[0] + EPSF * tx * RNDF);
        // Y finals
        float yvL = g_yval[TK];
        float ty = 0.0f;
        for (int k = 0; k < TK; k++) if (g_yval[k] == yvL) ty = 1.0f;
        float dy = 1.0f / (g_yval[0] - yvL + EPSF * ty * RNDF);
        for (int k = 0; k < TK; k++) {
            int r = g_yrow[k];
            out_final[r] = (g_yval[k] - yvL) * dy;
            out_ages[r]  = ages[r] + 1.0f;
        }
        // Z finals
        float zvL = g_zval[ZTK];
        float dz = 1.0f / (g_zval[0] - zvL);
        for (int k = 0; k < ZTK; k++) {
            int r = g_zrow[k];
            float f = (g_zval[k] - zvL) * dz;
            out_final[r] = f;
            out_z[r - (XS + NN)] = f;
            out_ages[r] = ages[r] + 1.0f;
        }
    }
}

// ---------------- K5: x finals + x ages ----------------
__global__ void k_xfinal(const float* __restrict__ ages, float* __restrict__ out_final,
                         float* __restrict__ out_ages) {
    int i = blockIdx.x * 256 + threadIdx.x;
    if (i < XS) {
        out_final[i] = g_resp[i] * g_inv_dx;
        if (i < XS - 1) out_ages[i] = ages[i] + 1.0f;
    }
}

// ---------------- K6: reduce mix_x partials; compute mix_y, mix_z ----------------
__global__ void k_mixyz(const float* __restrict__ neurons) {
    int c = blockIdx.x * 256 + threadIdx.x;
    if (c >= DD) return;
    float mx = 0.0f;
#pragma unroll
    for (int ch = 0; ch < NCHUNK; ch++) mx += g_mixx_part[ch][c];
    g_mix_x[c] = mx;
    float my = 0.0f;
#pragma unroll
    for (int k = 0; k < TK; k++) {
        int r = g_yrow[k];
        my = fmaf(g_w[r], __ldg(&neurons[(size_t)r * DD + c]), my);
    }
    g_mix_y[c] = my;
    float mz = 0.0f;
#pragma unroll
    for (int k = 0; k < ZTK; k++) {
        int r = g_zrow[k];
        mz = fmaf(g_w[r], __ldg(&neurons[(size_t)r * DD + c]), mz);
    }
    g_mix_z[c] = mz;
}

// ---------------- K7a: update x rows 0..XS-2 (8 rows/block; mix/inpt stay L1-hot) ----------------
__global__ void k_updx(const float* __restrict__ ages, float* __restrict__ out_neu) {
    int t = threadIdx.x;
    int r0 = blockIdx.x * 8;
    float invdx = g_inv_dx;
    for (int rr = 0; rr < 8; rr++) {
        int r = r0 + rr;
        if (r >= XS - 1) break;   // uniform across block
        float s = g_resp[r] * invdx / __ldg(&ages[r]);
        float v[25];
        float ssq = 0.0f;
#pragma unroll
        for (int j = 0; j < 25; j++) {
            int c = t + j * 256;
            if (c < DD) {
                float vv = fmaf(s, __ldg((const float*)&g_inpt[c]),
                                   __ldg((const float*)&g_mix_x[c]));
                v[j] = vv;
                ssq = fmaf(vv, vv, ssq);
            }
        }
        float tot = blockReduceSumB(ssq);
        float inv = 1.0f / (sqrtf(tot) + 1e-12f);
        float* dst = out_neu + (size_t)r * DD;
#pragma unroll
        for (int j = 0; j < 25; j++) {
            int c = t + j * 256;
            if (c < DD) dst[c] = v[j] * inv;
        }
    }
}

// ---------------- K7b: update 16 y rows + 8 z rows ----------------
__global__ void k_updyz(const float* __restrict__ ages, float* __restrict__ out_neu) {
    int b = blockIdx.x;
    int t = threadIdx.x;
    int r; float val; const float* mix;
    if (b < TK) { r = g_yrow[b]; val = g_yval[b]; mix = g_mix_y; }
    else        { r = g_zrow[b - TK]; val = g_zval[b - TK]; mix = g_mix_z; }
    float s = val / __ldg(&ages[r]);
    float v[25];
    float ssq = 0.0f;
#pragma unroll
    for (int j = 0; j < 25; j++) {
        int c = t + j * 256;
        if (c < DD) {
            float vv = fmaf(s, __ldg((const float*)&g_inpt[c]), __ldg(&mix[c]));
            v[j] = vv;
            ssq = fmaf(vv, vv, ssq);
        }
    }
    float tot = blockReduceSumB(ssq);
    float inv = 1.0f / (sqrtf(tot) + 1e-12f);
    float* dst = out_neu + (size_t)r * DD;
#pragma unroll
    for (int j = 0; j < 25; j++) {
        int c = t + j * 256;
        if (c < DD) dst[c] = v[j] * inv;
    }
}

// ---------------- launch ----------------
extern "C" void kernel_launch(void* const* d_in, const int* in_sizes, int n_in,
                              void* d_out, int out_size) {
    (void)in_sizes; (void)n_in; (void)out_size;
    const float* x       = (const float*)d_in[0];
    const float* z       = (const float*)d_in[1];
    const float* yresp   = (const float*)d_in[2];
    const float* neurons = (const float*)d_in[3];
    const float* ages    = (const float*)d_in[4];

    float* out       = (float*)d_out;
    float* out_z     = out;                                // 64
    float* out_final = out + ZS;                           // 6208
    float* out_neu   = out + ZS + DD;                      // 6208*6208
    float* out_ages  = out + ZS + DD + (size_t)DD * DD;    // 6208

    k_init<<<(DD + 255) / 256, 256>>>(x, z, yresp, ages, out_z, out_final, out_ages);
    k_matvec<<<DD, 256>>>((const float4*)neurons, out_neu);
    dim3 gmx((DD + 255) / 256, NCHUNK);
    k_mixx<<<gmx, 256>>>(neurons);
    k_topk<<<1, 256>>>(ages, out_z, out_final, out_ages);
    k_xfinal<<<(XS + 255) / 256, 256>>>(ages, out_final, out_ages);
    k_mixyz<<<(DD + 255) / 256, 256>>>(neurons);
    k_updx<<<(XS - 1 + 7) / 8, 256>>>(ages, out_neu);
    k_updyz<<<TK + ZTK, 256>>>(ages, out_neu);
}

// round 2
// speedup vs baseline: 1.2682x; 1.2682x over previous
#include <cuda_runtime.h>
#include <math.h>
#include <float.h>

#define XS 2048
#define NN 4096
#define ZS 64
#define DD 6208
#define NV4 1552          // DD/4
#define TK 16
#define ZTK 8
#define EPSF 1e-9f
#define RNDF 0.5f
#define NCHUNK 32

// ---------------- device scratch (no allocations allowed) ----------------
__device__ __align__(16) float g_inpt[DD];
__device__ float g_w[DD];                 // (ages-1)/ages
__device__ float g_resp[DD];
__device__ __align__(16) float g_mix_x[DD];
__device__ __align__(16) float g_mix_y[DD];
__device__ __align__(16) float g_mix_z[DD];
__device__ float g_mixx_part[NCHUNK][DD]; // deterministic partial sums
__device__ float g_yval[TK + 1];
__device__ int   g_yrow[TK + 1];
__device__ float g_zval[ZTK + 1];
__device__ int   g_zrow[ZTK + 1];
__device__ float g_inv_dx;

// ---------------- helpers ----------------
__device__ __forceinline__ float blockReduceSumB(float v) {
    __shared__ float red[8];
    __shared__ float bcast;
    int lane = threadIdx.x & 31;
    int wid  = threadIdx.x >> 5;
#pragma unroll
    for (int o = 16; o > 0; o >>= 1) v += __shfl_down_sync(0xffffffffu, v, o);
    if (lane == 0) red[wid] = v;
    __syncthreads();
    if (wid == 0) {
        float x = (lane < 8) ? red[lane] : 0.0f;
#pragma unroll
        for (int o = 4; o > 0; o >>= 1) x += __shfl_down_sync(0xffffffffu, x, o);
        if (lane == 0) bcast = x;
    }
    __syncthreads();
    return bcast;
}

// argmax with tie -> lowest index, warp scope
__device__ __forceinline__ void warpArgMax(float& bv, int& bi) {
#pragma unroll
    for (int o = 16; o > 0; o >>= 1) {
        float ov = __shfl_down_sync(0xffffffffu, bv, o);
        int   oi = __shfl_down_sync(0xffffffffu, bi, o);
        if (ov > bv || (ov == bv && oi < bi)) { bv = ov; bi = oi; }
    }
}

// ---------------- K1: build inpt, weights, zero final, copy ages ----------------
__global__ void k_init(const float* __restrict__ x, const float* __restrict__ z,
                       const float* __restrict__ yresp, const float* __restrict__ ages,
                       float* __restrict__ out_z, float* __restrict__ out_final,
                       float* __restrict__ out_ages) {
    int i = blockIdx.x * 256 + threadIdx.x;
    if (i < DD) {
        float v;
        if (i < XS)           v = x[i];
        else if (i < XS + NN) v = yresp[i - XS];
        else                  v = z[i - XS - NN];
        g_inpt[i] = v;
        float a = ages[i];
        g_w[i] = (a - 1.0f) / a;
        out_final[i] = 0.0f;
        out_ages[i]  = a;
    }
    if (i < ZS) out_z[i] = 0.0f;
}

// ---------------- K2: matvec + fused copy (skip rows < XS-1, rewritten later) ----------------
__global__ void k_matvec(const float4* __restrict__ neu4, float* __restrict__ out_neu) {
    int row = blockIdx.x;
    const float4* src = neu4 + (size_t)row * NV4;
    float4* dst = reinterpret_cast<float4*>(out_neu) + (size_t)row * NV4;
    const float4* ip = reinterpret_cast<const float4*>(g_inpt);
    int t = threadIdx.x;
    float acc = 0.0f;
    bool docopy = (row >= XS - 1);
#pragma unroll
    for (int j = 0; j < 7; j++) {
        int c = t + j * 256;
        if (c < NV4) {
            float4 v = __ldg(src + c);
            float4 w = ip[c];
            acc = fmaf(v.x, w.x, acc);
            acc = fmaf(v.y, w.y, acc);
            acc = fmaf(v.z, w.z, acc);
            acc = fmaf(v.w, w.w, acc);
            if (docopy) __stcs(dst + c, v);
        }
    }
    float tot = blockReduceSumB(acc);
    if (t == 0) g_resp[row] = tot;
}

// ---------------- K3: mix_x column partial sums (deterministic chunks) ----------------
__global__ void k_mixx(const float* __restrict__ neurons) {
    int c = blockIdx.x * 256 + threadIdx.x;
    int chunk = blockIdx.y;
    if (c >= DD) return;
    int r0 = chunk * 64;
    int r1 = min(r0 + 64, XS - 1);
    float acc = 0.0f;
    for (int r = r0; r < r1; r++)
        acc = fmaf(g_w[r], __ldg(&neurons[(size_t)r * DD + c]), acc);
    g_mixx_part[chunk][c] = acc;
}

// ---------------- K4: register-tournament top-k + x finals (1024 threads) ----------------
__global__ void k_topk(const float* __restrict__ ages, float* __restrict__ out_z,
                       float* __restrict__ out_final, float* __restrict__ out_ages) {
    __shared__ float wv[32];
    __shared__ int   wi[32];
    __shared__ float s_bv;
    __shared__ int   s_bi;
    __shared__ float s_invdx;

    int t    = threadIdx.x;       // 0..1023
    int lane = t & 31;
    int wid  = t >> 5;

    // ---- Y top-17: 4 register values per thread ----
    int base = t * 4;
    float v[4];
#pragma unroll
    for (int j = 0; j < 4; j++) v[j] = g_resp[XS + base + j];

    for (int k = 0; k < TK + 1; k++) {
        float bv = v[0]; int bi = base;
#pragma unroll
        for (int j = 1; j < 4; j++)
            if (v[j] > bv) { bv = v[j]; bi = base + j; }   // ascending idx: strict > keeps lowest
        warpArgMax(bv, bi);
        if (lane == 0) { wv[wid] = bv; wi[wid] = bi; }
        __syncthreads();
        if (wid == 0) {
            float rv2 = wv[lane]; int ri2 = wi[lane];
            warpArgMax(rv2, ri2);
            if (lane == 0) {
                s_bv = rv2; s_bi = ri2;
                g_yval[k] = rv2; g_yrow[k] = XS + ri2;
            }
        }
        __syncthreads();
        int bidx = s_bi;
        if ((bidx >> 2) == t) v[bidx & 3] = -FLT_MAX;
        // next wv write is gated by the first __syncthreads of the next iter,
        // and all threads have consumed s_bi before warp0 rewrites it -> safe
    }

    // ---- Z top-9: warp 0 only, shfl-only ----
    if (wid == 0) {
        float z0 = g_resp[XS + NN + lane];
        float z1 = g_resp[XS + NN + 32 + lane];
        for (int k = 0; k < ZTK + 1; k++) {
            float bv = z0; int bi = lane;
            if (z1 > bv) { bv = z1; bi = lane + 32; }
            warpArgMax(bv, bi);
            bv = __shfl_sync(0xffffffffu, bv, 0);
            bi = __shfl_sync(0xffffffffu, bi, 0);
            if (lane == 0) { g_zval[k] = bv; g_zrow[k] = XS + NN + bi; }
            if (bi == lane)      z0 = -FLT_MAX;
            if (bi == lane + 32) z1 = -FLT_MAX;
        }
    }

    // ---- X max + nonzero flag (2 per thread) ----
    float xa = g_resp[t], xb = g_resp[t + 1024];
    float m = fmaxf(xa, xb);
    int nz = (xa != 0.0f) | (xb != 0.0f);
    {
        float bv = m; int bi = nz;
#pragma unroll
        for (int o = 16; o > 0; o >>= 1) {
            bv = fmaxf(bv, __shfl_down_sync(0xffffffffu, bv, o));
            bi |= __shfl_down_sync(0xffffffffu, bi, o);
        }
        if (lane == 0) { wv[wid] = bv; wi[wid] = bi; }
    }
    __syncthreads();
    if (t == 0) {
        float bv = wv[0]; int bi = wi[0];
#pragma unroll
        for (int w2 = 1; w2 < 32; w2++) { bv = fmaxf(bv, wv[w2]); bi |= wi[w2]; }
        float tx = bi ? 0.0f : 1.0f;
        float inv = 1.0f / (bv + EPSF * tx * RNDF);
        s_invdx = inv;
        g_inv_dx = inv;

        // Y finals
        float yvL = g_yval[TK];
        float ty = 0.0f;
        for (int k = 0; k < TK; k++) if (g_yval[k] == yvL) ty = 1.0f;
        float dy = 1.0f / (g_yval[0] - yvL + EPSF * ty * RNDF);
        for (int k = 0; k < TK; k++) {
            int r = g_yrow[k];
            out_final[r] = (g_yval[k] - yvL) * dy;
            out_ages[r]  = ages[r] + 1.0f;
        }
        // Z finals
        float zvL = g_zval[ZTK];
        float dz = 1.0f / (g_zval[0] - zvL);
        for (int k = 0; k < ZTK; k++) {
            int r = g_zrow[k];
            float f = (g_zval[k] - zvL) * dz;
            out_final[r] = f;
            out_z[r - (XS + NN)] = f;
            out_ages[r] = ages[r] + 1.0f;
        }
    }
    __syncthreads();

    // ---- X finals + ages (fused; 2 per thread) ----
    float inv = s_invdx;
    out_final[t]        = xa * inv;
    out_final[t + 1024] = xb * inv;
    out_ages[t] = ages[t] + 1.0f;                      // t < 2047 always (t<=1023)
    if (t + 1024 < XS - 1) out_ages[t + 1024] = ages[t + 1024] + 1.0f;
}

// ---------------- K6: reduce mix_x partials; compute mix_y, mix_z ----------------
__global__ void k_mixyz(const float* __restrict__ neurons) {
    int c = blockIdx.x * 256 + threadIdx.x;
    if (c >= DD) return;
    float mx = 0.0f;
#pragma unroll
    for (int ch = 0; ch < NCHUNK; ch++) mx += g_mixx_part[ch][c];
    g_mix_x[c] = mx;
    float my = 0.0f;
#pragma unroll
    for (int k = 0; k < TK; k++) {
        int r = g_yrow[k];
        my = fmaf(g_w[r], __ldg(&neurons[(size_t)r * DD + c]), my);
    }
    g_mix_y[c] = my;
    float mz = 0.0f;
#pragma unroll
    for (int k = 0; k < ZTK; k++) {
        int r = g_zrow[k];
        mz = fmaf(g_w[r], __ldg(&neurons[(size_t)r * DD + c]), mz);
    }
    g_mix_z[c] = mz;
}

// ---------------- K7a: update x rows 0..XS-2 (8 rows/block) ----------------
__global__ void k_updx(const float* __restrict__ ages, float* __restrict__ out_neu) {
    int t = threadIdx.x;
    int r0 = blockIdx.x * 8;
    float invdx = g_inv_dx;
    for (int rr = 0; rr < 8; rr++) {
        int r = r0 + rr;
        if (r >= XS - 1) break;   // uniform across block
        float s = g_resp[r] * invdx / __ldg(&ages[r]);
        float v[25];
        float ssq = 0.0f;
#pragma unroll
        for (int j = 0; j < 25; j++) {
            int c = t + j * 256;
            if (c < DD) {
                float vv = fmaf(s, __ldg((const float*)&g_inpt[c]),
                                   __ldg((const float*)&g_mix_x[c]));
                v[j] = vv;
                ssq = fmaf(vv, vv, ssq);
            }
        }
        float tot = blockReduceSumB(ssq);
        float inv = 1.0f / (sqrtf(tot) + 1e-12f);
        float* dst = out_neu + (size_t)r * DD;
#pragma unroll
        for (int j = 0; j < 25; j++) {
            int c = t + j * 256;
            if (c < DD) dst[c] = v[j] * inv;
        }
    }
}

// ---------------- K7b: update 16 y rows + 8 z rows ----------------
__global__ void k_updyz(const float* __restrict__ ages, float* __restrict__ out_neu) {
    int b = blockIdx.x;
    int t = threadIdx.x;
    int r; float val; const float* mix;
    if (b < TK) { r = g_yrow[b]; val = g_yval[b]; mix = g_mix_y; }
    else        { r = g_zrow[b - TK]; val = g_zval[b - TK]; mix = g_mix_z; }
    float s = val / __ldg(&ages[r]);
    float v[25];
    float ssq = 0.0f;
#pragma unroll
    for (int j = 0; j < 25; j++) {
        int c = t + j * 256;
        if (c < DD) {
            float vv = fmaf(s, __ldg((const float*)&g_inpt[c]), __ldg(&mix[c]));
            v[j] = vv;
            ssq = fmaf(vv, vv, ssq);
        }
    }
    float tot = blockReduceSumB(ssq);
    float inv = 1.0f / (sqrtf(tot) + 1e-12f);
    float* dst = out_neu + (size_t)r * DD;
#pragma unroll
    for (int j = 0; j < 25; j++) {
        int c = t + j * 256;
        if (c < DD) dst[c] = v[j] * inv;
    }
}

// ---------------- launch ----------------
extern "C" void kernel_launch(void* const* d_in, const int* in_sizes, int n_in,
                              void* d_out, int out_size) {
    (void)in_sizes; (void)n_in; (void)out_size;
    const float* x       = (const float*)d_in[0];
    const float* z       = (const float*)d_in[1];
    const float* yresp   = (const float*)d_in[2];
    const float* neurons = (const float*)d_in[3];
    const float* ages    = (const float*)d_in[4];

    float* out       = (float*)d_out;
    float* out_z     = out;                                // 64
    float* out_final = out + ZS;                           // 6208
    float* out_neu   = out + ZS + DD;                      // 6208*6208
    float* out_ages  = out + ZS + DD + (size_t)DD * DD;    // 6208

    k_init<<<(DD + 255) / 256, 256>>>(x, z, yresp, ages, out_z, out_final, out_ages);
    k_matvec<<<DD, 256>>>((const float4*)neurons, out_neu);
    dim3 gmx((DD + 255) / 256, NCHUNK);
    k_mixx<<<gmx, 256>>>(neurons);
    k_topk<<<1, 1024>>>(ages, out_z, out_final, out_ages);
    k_mixyz<<<(DD + 255) / 256, 256>>>(neurons);
    k_updx<<<(XS - 1 + 7) / 8, 256>>>(ages, out_neu);
    k_updyz<<<TK + ZTK, 256>>>(ages, out_neu);
}

// round 3
// speedup vs baseline: 1.3421x; 1.0582x over previous
#include <cuda_runtime.h>
#include <math.h>
#include <float.h>

#define XS 2048
#define NN 4096
#define ZS 64
#define DD 6208
#define NV4 1552          // DD/4
#define TK 16
#define ZTK 8
#define EPSF 1e-9f
#define RNDF 0.5f
#define NCHUNK 32

// ---------------- device scratch (no allocations allowed) ----------------
__device__ __align__(16) float g_inpt[DD];
__device__ float g_w[DD];                 // (ages-1)/ages
__device__ __align__(16) float g_resp[DD];
__device__ __align__(16) float g_mix_x[DD];
__device__ __align__(16) float g_mix_y[DD];
__device__ __align__(16) float g_mix_z[DD];
__device__ float g_mixx_part[NCHUNK][DD]; // deterministic partial sums
__device__ float g_yval[TK + 1];
__device__ int   g_yrow[TK + 1];
__device__ float g_zval[ZTK + 1];
__device__ int   g_zrow[ZTK + 1];
__device__ float g_inv_dx;

// ---------------- helpers ----------------
__device__ __forceinline__ float blockReduceSumB(float v) {
    __shared__ float red[8];
    __shared__ float bcast;
    int lane = threadIdx.x & 31;
    int wid  = threadIdx.x >> 5;
#pragma unroll
    for (int o = 16; o > 0; o >>= 1) v += __shfl_down_sync(0xffffffffu, v, o);
    if (lane == 0) red[wid] = v;
    __syncthreads();
    if (wid == 0) {
        float x = (lane < 8) ? red[lane] : 0.0f;
#pragma unroll
        for (int o = 4; o > 0; o >>= 1) x += __shfl_down_sync(0xffffffffu, x, o);
        if (lane == 0) bcast = x;
    }
    __syncthreads();
    return bcast;
}

// argmax with tie -> lowest index, warp scope (result valid on lane 0)
__device__ __forceinline__ void warpArgMax(float& bv, int& bi) {
#pragma unroll
    for (int o = 16; o > 0; o >>= 1) {
        float ov = __shfl_down_sync(0xffffffffu, bv, o);
        int   oi = __shfl_down_sync(0xffffffffu, bi, o);
        if (ov > bv || (ov == bv && oi < bi)) { bv = ov; bi = oi; }
    }
}

// ---------------- K1: build inpt, weights, zero final, copy ages ----------------
__global__ void k_init(const float* __restrict__ x, const float* __restrict__ z,
                       const float* __restrict__ yresp, const float* __restrict__ ages,
                       float* __restrict__ out_z, float* __restrict__ out_final,
                       float* __restrict__ out_ages) {
    int i = blockIdx.x * 256 + threadIdx.x;
    if (i < DD) {
        float v;
        if (i < XS)           v = x[i];
        else if (i < XS + NN) v = yresp[i - XS];
        else                  v = z[i - XS - NN];
        g_inpt[i] = v;
        float a = ages[i];
        g_w[i] = (a - 1.0f) / a;
        out_final[i] = 0.0f;
        out_ages[i]  = a;
    }
    if (i < ZS) out_z[i] = 0.0f;
}

// ---------------- K2: matvec + fused copy (skip rows < XS-1, rewritten later) ----------------
__global__ void k_matvec(const float4* __restrict__ neu4, float* __restrict__ out_neu) {
    int row = blockIdx.x;
    const float4* src = neu4 + (size_t)row * NV4;
    float4* dst = reinterpret_cast<float4*>(out_neu) + (size_t)row * NV4;
    const float4* ip = reinterpret_cast<const float4*>(g_inpt);
    int t = threadIdx.x;
    float acc = 0.0f;
    bool docopy = (row >= XS - 1);
#pragma unroll
    for (int j = 0; j < 7; j++) {
        int c = t + j * 256;
        if (c < NV4) {
            float4 v = __ldg(src + c);
            float4 w = ip[c];
            acc = fmaf(v.x, w.x, acc);
            acc = fmaf(v.y, w.y, acc);
            acc = fmaf(v.z, w.z, acc);
            acc = fmaf(v.w, w.w, acc);
            if (docopy) __stcs(dst + c, v);
        }
    }
    float tot = blockReduceSumB(acc);
    if (t == 0) g_resp[row] = tot;
}

// ---------------- K3: mix_x column partial sums (deterministic chunks) ----------------
__global__ void k_mixx(const float* __restrict__ neurons) {
    int c = blockIdx.x * 256 + threadIdx.x;
    int chunk = blockIdx.y;
    if (c >= DD) return;
    int r0 = chunk * 64;
    int r1 = min(r0 + 64, XS - 1);
    float acc = 0.0f;
    for (int r = r0; r < r1; r++)
        acc = fmaf(g_w[r], __ldg(&neurons[(size_t)r * DD + c]), acc);
    g_mixx_part[chunk][c] = acc;
}

// ---------------- K4: warp-local tournament + 32-way merge top-k ----------------
__global__ void k_topk(const float* __restrict__ ages, float* __restrict__ out_z,
                       float* __restrict__ out_final, float* __restrict__ out_ages) {
    __shared__ float s_cv[32][TK + 1];   // per-warp sorted top-17 values
    __shared__ int   s_ci[32][TK + 1];   // global row indices
    __shared__ float s_xv[32];
    __shared__ int   s_xnz[32];
    __shared__ float s_yv[TK + 1];
    __shared__ int   s_yr[TK + 1];
    __shared__ float s_zv[ZTK + 1];
    __shared__ int   s_zr[ZTK + 1];
    __shared__ float s_invdx;

    int t    = threadIdx.x;       // 0..1023
    int lane = t & 31;
    int wid  = t >> 5;

    // ---- X partials (issue loads early) ----
    float xa = g_resp[t], xb = g_resp[t + 1024];
    {
        float bv = fmaxf(xa, xb);
        int   nz = (xa != 0.0f) | (xb != 0.0f);
#pragma unroll
        for (int o = 16; o > 0; o >>= 1) {
            bv  = fmaxf(bv, __shfl_down_sync(0xffffffffu, bv, o));
            nz |= __shfl_down_sync(0xffffffffu, nz, o);
        }
        if (lane == 0) { s_xv[wid] = bv; s_xnz[wid] = nz; }
    }

    // ---- Y stage A: each warp extracts sorted top-17 of its 128 values ----
    {
        int gbase = XS + wid * 128 + lane * 4;
        float4 vy = *(const float4*)&g_resp[gbase];
        float v[4] = {vy.x, vy.y, vy.z, vy.w};
        int baseL = lane * 4;
#pragma unroll 1
        for (int k = 0; k < TK + 1; k++) {
            float bv = v[0]; int bi = baseL;
#pragma unroll
            for (int j = 1; j < 4; j++)
                if (v[j] > bv) { bv = v[j]; bi = baseL + j; }  // strict > keeps lowest idx
            warpArgMax(bv, bi);
            bv = __shfl_sync(0xffffffffu, bv, 0);
            bi = __shfl_sync(0xffffffffu, bi, 0);
            if (lane == 0) { s_cv[wid][k] = bv; s_ci[wid][k] = XS + wid * 128 + bi; }
            if ((bi >> 2) == lane) v[bi & 3] = -FLT_MAX;
        }
    }
    __syncthreads();

    // ---- concurrent warp roles ----
    if (wid == 0) {
        // Stage B: 32-way merge of sorted per-warp lists
        int p = 0;
        float hv = s_cv[lane][0];
        int   hi = s_ci[lane][0];
#pragma unroll 1
        for (int k = 0; k < TK + 1; k++) {
            float bv = hv; int bi = hi;
            warpArgMax(bv, bi);
            bv = __shfl_sync(0xffffffffu, bv, 0);
            bi = __shfl_sync(0xffffffffu, bi, 0);
            if (lane == 0) { s_yv[k] = bv; s_yr[k] = bi; g_yval[k] = bv; g_yrow[k] = bi; }
            if (hi == bi) {
                p++;
                if (p < TK + 1) { hv = s_cv[lane][p]; hi = s_ci[lane][p]; }
                else            { hv = -FLT_MAX; hi = 1 << 30; }
            }
        }
    } else if (wid == 1) {
        // Z top-9, shfl-only
        float z0 = g_resp[XS + NN + lane];
        float z1 = g_resp[XS + NN + 32 + lane];
#pragma unroll 1
        for (int k = 0; k < ZTK + 1; k++) {
            float bv = z0; int bi = lane;
            if (z1 > bv) { bv = z1; bi = lane + 32; }
            warpArgMax(bv, bi);
            bv = __shfl_sync(0xffffffffu, bv, 0);
            bi = __shfl_sync(0xffffffffu, bi, 0);
            if (lane == 0) { s_zv[k] = bv; s_zr[k] = XS + NN + bi;
                             g_zval[k] = bv; g_zrow[k] = XS + NN + bi; }
            if (bi == lane)      z0 = -FLT_MAX;
            if (bi == lane + 32) z1 = -FLT_MAX;
        }
    } else if (wid == 2) {
        // X final reduce
        float bv = s_xv[lane]; int nz = s_xnz[lane];
#pragma unroll
        for (int o = 16; o > 0; o >>= 1) {
            bv  = fmaxf(bv, __shfl_down_sync(0xffffffffu, bv, o));
            nz |= __shfl_down_sync(0xffffffffu, nz, o);
        }
        if (lane == 0) {
            float tx = nz ? 0.0f : 1.0f;
            float inv = 1.0f / (bv + EPSF * tx * RNDF);
            s_invdx = inv;
            g_inv_dx = inv;
        }
    }
    __syncthreads();

    // ---- scalar finals for y/z ----
    if (t == 0) {
        float yvL = s_yv[TK];
        float ty = 0.0f;
#pragma unroll
        for (int k = 0; k < TK; k++) if (s_yv[k] == yvL) ty = 1.0f;
        float dy = 1.0f / (s_yv[0] - yvL + EPSF * ty * RNDF);
#pragma unroll
        for (int k = 0; k < TK; k++) {
            int r = s_yr[k];
            out_final[r] = (s_yv[k] - yvL) * dy;
            out_ages[r]  = ages[r] + 1.0f;
        }
        float zvL = s_zv[ZTK];
        float dz = 1.0f / (s_zv[0] - zvL);
#pragma unroll
        for (int k = 0; k < ZTK; k++) {
            int r = s_zr[k];
            float f = (s_zv[k] - zvL) * dz;
            out_final[r] = f;
            out_z[r - (XS + NN)] = f;
            out_ages[r] = ages[r] + 1.0f;
        }
    }

    // ---- X finals + ages ----
    float inv = s_invdx;
    out_final[t]        = xa * inv;
    out_final[t + 1024] = xb * inv;
    out_ages[t] = ages[t] + 1.0f;                      // t <= 1023 < XS-1
    if (t + 1024 < XS - 1) out_ages[t + 1024] = ages[t + 1024] + 1.0f;
}

// ---------------- K6: reduce mix_x partials; compute mix_y, mix_z ----------------
__global__ void k_mixyz(const float* __restrict__ neurons) {
    int c = blockIdx.x * 256 + threadIdx.x;
    if (c >= DD) return;
    float mx = 0.0f;
#pragma unroll
    for (int ch = 0; ch < NCHUNK; ch++) mx += g_mixx_part[ch][c];
    g_mix_x[c] = mx;
    float my = 0.0f;
#pragma unroll
    for (int k = 0; k < TK; k++) {
        int r = g_yrow[k];
        my = fmaf(g_w[r], __ldg(&neurons[(size_t)r * DD + c]), my);
    }
    g_mix_y[c] = my;
    float mz = 0.0f;
#pragma unroll
    for (int k = 0; k < ZTK; k++) {
        int r = g_zrow[k];
        mz = fmaf(g_w[r], __ldg(&neurons[(size_t)r * DD + c]), mz);
    }
    g_mix_z[c] = mz;
}

// ---------------- K7a: update x rows 0..XS-2 (8 rows/block) ----------------
__global__ void k_updx(const float* __restrict__ ages, float* __restrict__ out_neu) {
    int t = threadIdx.x;
    int r0 = blockIdx.x * 8;
    float invdx = g_inv_dx;
    for (int rr = 0; rr < 8; rr++) {
        int r = r0 + rr;
        if (r >= XS - 1) break;   // uniform across block
        float s = g_resp[r] * invdx / __ldg(&ages[r]);
        float v[25];
        float ssq = 0.0f;
#pragma unroll
        for (int j = 0; j < 25; j++) {
            int c = t + j * 256;
            if (c < DD) {
                float vv = fmaf(s, __ldg((const float*)&g_inpt[c]),
                                   __ldg((const float*)&g_mix_x[c]));
                v[j] = vv;
                ssq = fmaf(vv, vv, ssq);
            }
        }
        float tot = blockReduceSumB(ssq);
        float inv = 1.0f / (sqrtf(tot) + 1e-12f);
        float* dst = out_neu + (size_t)r * DD;
#pragma unroll
        for (int j = 0; j < 25; j++) {
            int c = t + j * 256;
            if (c < DD) dst[c] = v[j] * inv;
        }
    }
}

// ---------------- K7b: update 16 y rows + 8 z rows ----------------
__global__ void k_updyz(const float* __restrict__ ages, float* __restrict__ out_neu) {
    int b = blockIdx.x;
    int t = threadIdx.x;
    int r; float val; const float* mix;
    if (b < TK) { r = g_yrow[b]; val = g_yval[b]; mix = g_mix_y; }
    else        { r = g_zrow[b - TK]; val = g_zval[b - TK]; mix = g_mix_z; }
    float s = val / __ldg(&ages[r]);
    float v[25];
    float ssq = 0.0f;
#pragma unroll
    for (int j = 0; j < 25; j++) {
        int c = t + j * 256;
        if (c < DD) {
            float vv = fmaf(s, __ldg((const float*)&g_inpt[c]), __ldg(&mix[c]));
            v[j] = vv;
            ssq = fmaf(vv, vv, ssq);
        }
    }
    float tot = blockReduceSumB(ssq);
    float inv = 1.0f / (sqrtf(tot) + 1e-12f);
    float* dst = out_neu + (size_t)r * DD;
#pragma unroll
    for (int j = 0; j < 25; j++) {
        int c = t + j * 256;
        if (c < DD) dst[c] = v[j] * inv;
    }
}

// ---------------- launch ----------------
extern "C" void kernel_launch(void* const* d_in, const int* in_sizes, int n_in,
                              void* d_out, int out_size) {
    (void)in_sizes; (void)n_in; (void)out_size;
    const float* x       = (const float*)d_in[0];
    const float* z       = (const float*)d_in[1];
    const float* yresp   = (const float*)d_in[2];
    const float* neurons = (const float*)d_in[3];
    const float* ages    = (const float*)d_in[4];

    float* out       = (float*)d_out;
    float* out_z     = out;                                // 64
    float* out_final = out + ZS;                           // 6208
    float* out_neu   = out + ZS + DD;                      // 6208*6208
    float* out_ages  = out + ZS + DD + (size_t)DD * DD;    // 6208

    k_init<<<(DD + 255) / 256, 256>>>(x, z, yresp, ages, out_z, out_final, out_ages);
    k_matvec<<<DD, 256>>>((const float4*)neurons, out_neu);
    dim3 gmx((DD + 255) / 256, NCHUNK);
    k_mixx<<<gmx, 256>>>(neurons);
    k_topk<<<1, 1024>>>(ages, out_z, out_final, out_ages);
    k_mixyz<<<(DD + 255) / 256, 256>>>(neurons);
    k_updx<<<(XS - 1 + 7) / 8, 256>>>(ages, out_neu);
    k_updyz<<<TK + ZTK, 256>>>(ages, out_neu);
}

// round 4
// speedup vs baseline: 1.4085x; 1.0495x over previous
#include <cuda_runtime.h>
#include <math.h>
#include <float.h>

#define XS 2048
#define NN 4096
#define ZS 64
#define DD 6208
#define NV4 1552          // DD/4
#define TK 16
#define ZTK 8
#define EPSF 1e-9f
#define RNDF 0.5f
#define NCHUNK 32

// ---------------- device scratch (no allocations allowed) ----------------
__device__ __align__(16) float g_inpt[DD];
__device__ float g_w[DD];                 // (ages-1)/ages
__device__ __align__(16) float g_resp[DD];
__device__ __align__(16) float g_mix_x[DD];
__device__ __align__(16) float g_mix_y[DD];
__device__ __align__(16) float g_mix_z[DD];
__device__ float g_mixx_part[NCHUNK][DD]; // deterministic partial sums
__device__ float g_cval[32][TK + 1];      // per-warp sorted y candidates
__device__ int   g_crow[32][TK + 1];
__device__ float g_yval[TK + 1];
__device__ int   g_yrow[TK + 1];
__device__ float g_zval[ZTK + 1];
__device__ int   g_zrow[ZTK + 1];
__device__ float g_inv_dx;

// ---------------- helpers ----------------
__device__ __forceinline__ float blockReduceSumB(float v) {
    __shared__ float red[8];
    __shared__ float bcast;
    int lane = threadIdx.x & 31;
    int wid  = threadIdx.x >> 5;
#pragma unroll
    for (int o = 16; o > 0; o >>= 1) v += __shfl_down_sync(0xffffffffu, v, o);
    if (lane == 0) red[wid] = v;
    __syncthreads();
    if (wid == 0) {
        float x = (lane < 8) ? red[lane] : 0.0f;
#pragma unroll
        for (int o = 4; o > 0; o >>= 1) x += __shfl_down_sync(0xffffffffu, x, o);
        if (lane == 0) bcast = x;
    }
    __syncthreads();
    return bcast;
}

// argmax with tie -> lowest index, warp scope (result valid on lane 0)
__device__ __forceinline__ void warpArgMax(float& bv, int& bi) {
#pragma unroll
    for (int o = 16; o > 0; o >>= 1) {
        float ov = __shfl_down_sync(0xffffffffu, bv, o);
        int   oi = __shfl_down_sync(0xffffffffu, bi, o);
        if (ov > bv || (ov == bv && oi < bi)) { bv = ov; bi = oi; }
    }
}

// ---------------- K1: build inpt, weights, zero final, copy ages ----------------
__global__ void k_init(const float* __restrict__ x, const float* __restrict__ z,
                       const float* __restrict__ yresp, const float* __restrict__ ages,
                       float* __restrict__ out_z, float* __restrict__ out_final,
                       float* __restrict__ out_ages) {
    int i = blockIdx.x * 256 + threadIdx.x;
    if (i < DD) {
        float v;
        if (i < XS)           v = x[i];
        else if (i < XS + NN) v = yresp[i - XS];
        else                  v = z[i - XS - NN];
        g_inpt[i] = v;
        float a = ages[i];
        g_w[i] = (a - 1.0f) / a;
        out_final[i] = 0.0f;
        out_ages[i]  = a;
    }
    if (i < ZS) out_z[i] = 0.0f;
}

// ---------------- K2: matvec + fused copy (skip rows < XS-1, rewritten later) ----------------
__global__ void k_matvec(const float4* __restrict__ neu4, float* __restrict__ out_neu) {
    int row = blockIdx.x;
    const float4* src = neu4 + (size_t)row * NV4;
    float4* dst = reinterpret_cast<float4*>(out_neu) + (size_t)row * NV4;
    const float4* ip = reinterpret_cast<const float4*>(g_inpt);
    int t = threadIdx.x;
    float acc = 0.0f;
    bool docopy = (row >= XS - 1);
#pragma unroll
    for (int j = 0; j < 7; j++) {
        int c = t + j * 256;
        if (c < NV4) {
            float4 v = __ldg(src + c);
            float4 w = ip[c];
            acc = fmaf(v.x, w.x, acc);
            acc = fmaf(v.y, w.y, acc);
            acc = fmaf(v.z, w.z, acc);
            acc = fmaf(v.w, w.w, acc);
            if (docopy) __stcs(dst + c, v);
        }
    }
    float tot = blockReduceSumB(acc);
    if (t == 0) g_resp[row] = tot;
}

// ---------------- K3: mix_x column partial sums (deterministic chunks) ----------------
__global__ void k_mixx(const float* __restrict__ neurons) {
    int c = blockIdx.x * 256 + threadIdx.x;
    int chunk = blockIdx.y;
    if (c >= DD) return;
    int r0 = chunk * 64;
    int r1 = min(r0 + 64, XS - 1);
    float acc = 0.0f;
    for (int r = r0; r < r1; r++)
        acc = fmaf(g_w[r], __ldg(&neurons[(size_t)r * DD + c]), acc);
    g_mixx_part[chunk][c] = acc;
}

// ---------------- K4a: per-warp sorted y top-17 (32 blocks x 1 warp) ----------------
__global__ void k_ycand() {
    int w    = blockIdx.x;       // 0..31
    int lane = threadIdx.x;      // 0..31
    int gbase = XS + w * 128 + lane * 4;
    float4 vy = *(const float4*)&g_resp[gbase];
    float v[4] = {vy.x, vy.y, vy.z, vy.w};
    int baseL = lane * 4;
#pragma unroll 1
    for (int k = 0; k < TK + 1; k++) {
        float bv = v[0]; int bi = baseL;
#pragma unroll
        for (int j = 1; j < 4; j++)
            if (v[j] > bv) { bv = v[j]; bi = baseL + j; }   // strict > keeps lowest idx
        warpArgMax(bv, bi);
        bv = __shfl_sync(0xffffffffu, bv, 0);
        bi = __shfl_sync(0xffffffffu, bi, 0);
        if (lane == 0) { g_cval[w][k] = bv; g_crow[w][k] = XS + w * 128 + bi; }
        if ((bi >> 2) == lane) v[bi & 3] = -FLT_MAX;
    }
}

// ---------------- K4b: merge + z top-9 + x max + all scalar finals ----------------
__global__ void k_final(const float* __restrict__ ages, float* __restrict__ out_z,
                        float* __restrict__ out_final, float* __restrict__ out_ages) {
    __shared__ float s_cv[32][TK + 1];
    __shared__ int   s_ci[32][TK + 1];
    __shared__ float s_xv[32];
    __shared__ int   s_xnz[32];
    __shared__ float s_yv[TK + 1];
    __shared__ int   s_yr[TK + 1];
    __shared__ float s_zv[ZTK + 1];
    __shared__ int   s_zr[ZTK + 1];
    __shared__ float s_invdx;

    int t    = threadIdx.x;       // 0..1023
    int lane = t & 31;
    int wid  = t >> 5;

    // cooperative candidate load (32*17 = 544 elements)
    if (t < 32 * (TK + 1)) {
        ((float*)s_cv)[t] = ((const float*)g_cval)[t];
        ((int*)s_ci)[t]   = ((const int*)g_crow)[t];
    }

    // ---- X partials ----
    float xa = g_resp[t], xb = g_resp[t + 1024];
    {
        float bv = fmaxf(xa, xb);
        int   nz = (xa != 0.0f) | (xb != 0.0f);
#pragma unroll
        for (int o = 16; o > 0; o >>= 1) {
            bv  = fmaxf(bv, __shfl_down_sync(0xffffffffu, bv, o));
            nz |= __shfl_down_sync(0xffffffffu, nz, o);
        }
        if (lane == 0) { s_xv[wid] = bv; s_xnz[wid] = nz; }
    }
    __syncthreads();

    // ---- concurrent warp roles ----
    if (wid == 0) {
        // 32-way merge of sorted per-warp lists
        int p = 0;
        float hv = s_cv[lane][0];
        int   hi = s_ci[lane][0];
#pragma unroll 1
        for (int k = 0; k < TK + 1; k++) {
            float bv = hv; int bi = hi;
            warpArgMax(bv, bi);
            bv = __shfl_sync(0xffffffffu, bv, 0);
            bi = __shfl_sync(0xffffffffu, bi, 0);
            if (lane == 0) { s_yv[k] = bv; s_yr[k] = bi; g_yval[k] = bv; g_yrow[k] = bi; }
            if (hi == bi) {
                p++;
                if (p < TK + 1) { hv = s_cv[lane][p]; hi = s_ci[lane][p]; }
                else            { hv = -FLT_MAX; hi = 1 << 30; }
            }
        }
    } else if (wid == 1) {
        // Z top-9, shfl-only
        float z0 = g_resp[XS + NN + lane];
        float z1 = g_resp[XS + NN + 32 + lane];
#pragma unroll 1
        for (int k = 0; k < ZTK + 1; k++) {
            float bv = z0; int bi = lane;
            if (z1 > bv) { bv = z1; bi = lane + 32; }
            warpArgMax(bv, bi);
            bv = __shfl_sync(0xffffffffu, bv, 0);
            bi = __shfl_sync(0xffffffffu, bi, 0);
            if (lane == 0) { s_zv[k] = bv; s_zr[k] = XS + NN + bi;
                             g_zval[k] = bv; g_zrow[k] = XS + NN + bi; }
            if (bi == lane)      z0 = -FLT_MAX;
            if (bi == lane + 32) z1 = -FLT_MAX;
        }
    } else if (wid == 2) {
        // X final reduce
        float bv = s_xv[lane]; int nz = s_xnz[lane];
#pragma unroll
        for (int o = 16; o > 0; o >>= 1) {
            bv  = fmaxf(bv, __shfl_down_sync(0xffffffffu, bv, o));
            nz |= __shfl_down_sync(0xffffffffu, nz, o);
        }
        if (lane == 0) {
            float tx = nz ? 0.0f : 1.0f;
            float inv = 1.0f / (bv + EPSF * tx * RNDF);
            s_invdx = inv;
            g_inv_dx = inv;
        }
    }
    __syncthreads();

    // ---- scalar finals for y/z ----
    if (t == 0) {
        float yvL = s_yv[TK];
        float ty = 0.0f;
#pragma unroll
        for (int k = 0; k < TK; k++) if (s_yv[k] == yvL) ty = 1.0f;
        float dy = 1.0f / (s_yv[0] - yvL + EPSF * ty * RNDF);
#pragma unroll
        for (int k = 0; k < TK; k++) {
            int r = s_yr[k];
            out_final[r] = (s_yv[k] - yvL) * dy;
            out_ages[r]  = ages[r] + 1.0f;
        }
        float zvL = s_zv[ZTK];
        float dz = 1.0f / (s_zv[0] - zvL);
#pragma unroll
        for (int k = 0; k < ZTK; k++) {
            int r = s_zr[k];
            float f = (s_zv[k] - zvL) * dz;
            out_final[r] = f;
            out_z[r - (XS + NN)] = f;
            out_ages[r] = ages[r] + 1.0f;
        }
    }

    // ---- X finals + ages ----
    float inv = s_invdx;
    out_final[t]        = xa * inv;
    out_final[t + 1024] = xb * inv;
    out_ages[t] = ages[t] + 1.0f;                      // t <= 1023 < XS-1
    if (t + 1024 < XS - 1) out_ages[t + 1024] = ages[t + 1024] + 1.0f;
}

// ---------------- K6: reduce mix_x partials; compute mix_y, mix_z ----------------
__global__ void k_mixyz(const float* __restrict__ neurons) {
    int c = blockIdx.x * 256 + threadIdx.x;
    if (c >= DD) return;
    float mx = 0.0f;
#pragma unroll
    for (int ch = 0; ch < NCHUNK; ch++) mx += g_mixx_part[ch][c];
    g_mix_x[c] = mx;
    float my = 0.0f;
#pragma unroll
    for (int k = 0; k < TK; k++) {
        int r = g_yrow[k];
        my = fmaf(g_w[r], __ldg(&neurons[(size_t)r * DD + c]), my);
    }
    g_mix_y[c] = my;
    float mz = 0.0f;
#pragma unroll
    for (int k = 0; k < ZTK; k++) {
        int r = g_zrow[k];
        mz = fmaf(g_w[r], __ldg(&neurons[(size_t)r * DD + c]), mz);
    }
    g_mix_z[c] = mz;
}

// ---------------- K7a: update x rows 0..XS-2 (4 rows/block) ----------------
__global__ void k_updx(const float* __restrict__ ages, float* __restrict__ out_neu) {
    int t = threadIdx.x;
    int r0 = blockIdx.x * 4;
    float invdx = g_inv_dx;
    for (int rr = 0; rr < 4; rr++) {
        int r = r0 + rr;
        if (r >= XS - 1) break;   // uniform across block
        float s = g_resp[r] * invdx / __ldg(&ages[r]);
        float v[25];
        float ssq = 0.0f;
#pragma unroll
        for (int j = 0; j < 25; j++) {
            int c = t + j * 256;
            if (c < DD) {
                float vv = fmaf(s, __ldg((const float*)&g_inpt[c]),
                                   __ldg((const float*)&g_mix_x[c]));
                v[j] = vv;
                ssq = fmaf(vv, vv, ssq);
            }
        }
        float tot = blockReduceSumB(ssq);
        float inv = 1.0f / (sqrtf(tot) + 1e-12f);
        float* dst = out_neu + (size_t)r * DD;
#pragma unroll
        for (int j = 0; j < 25; j++) {
            int c = t + j * 256;
            if (c < DD) __stcs(&dst[c], v[j] * inv);
        }
    }
}

// ---------------- K7b: update 16 y rows + 8 z rows ----------------
__global__ void k_updyz(const float* __restrict__ ages, float* __restrict__ out_neu) {
    int b = blockIdx.x;
    int t = threadIdx.x;
    int r; float val; const float* mix;
    if (b < TK) { r = g_yrow[b]; val = g_yval[b]; mix = g_mix_y; }
    else        { r = g_zrow[b - TK]; val = g_zval[b - TK]; mix = g_mix_z; }
    float s = val / __ldg(&ages[r]);
    float v[25];
    float ssq = 0.0f;
#pragma unroll
    for (int j = 0; j < 25; j++) {
        int c = t + j * 256;
        if (c < DD) {
            float vv = fmaf(s, __ldg((const float*)&g_inpt[c]), __ldg(&mix[c]));
            v[j] = vv;
            ssq = fmaf(vv, vv, ssq);
        }
    }
    float tot = blockReduceSumB(ssq);
    float inv = 1.0f / (sqrtf(tot) + 1e-12f);
    float* dst = out_neu + (size_t)r * DD;
#pragma unroll
    for (int j = 0; j < 25; j++) {
        int c = t + j * 256;
        if (c < DD) __stcs(&dst[c], v[j] * inv);
    }
}

// ---------------- launch ----------------
extern "C" void kernel_launch(void* const* d_in, const int* in_sizes, int n_in,
                              void* d_out, int out_size) {
    (void)in_sizes; (void)n_in; (void)out_size;
    const float* x       = (const float*)d_in[0];
    const float* z       = (const float*)d_in[1];
    const float* yresp   = (const float*)d_in[2];
    const float* neurons = (const float*)d_in[3];
    const float* ages    = (const float*)d_in[4];

    float* out       = (float*)d_out;
    float* out_z     = out;                                // 64
    float* out_final = out + ZS;                           // 6208
    float* out_neu   = out + ZS + DD;                      // 6208*6208
    float* out_ages  = out + ZS + DD + (size_t)DD * DD;    // 6208

    k_init<<<(DD + 255) / 256, 256>>>(x, z, yresp, ages, out_z, out_final, out_ages);
    k_matvec<<<DD, 256>>>((const float4*)neurons, out_neu);
    k_ycand<<<32, 32>>>();
    dim3 gmx((DD + 255) / 256, NCHUNK);
    k_mixx<<<gmx, 256>>>(neurons);
    k_final<<<1, 1024>>>(ages, out_z, out_final, out_ages);
    k_mixyz<<<(DD + 255) / 256, 256>>>(neurons);
    k_updx<<<(XS - 1 + 3) / 4, 256>>>(ages, out_neu);
    k_updyz<<<TK + ZTK, 256>>>(ages, out_neu);
}